// round 4
// baseline (speedup 1.0000x reference)
#include <cuda_runtime.h>
#include <cuda_bf16.h>
#include <cstdint>

// Problem constants
#define N_PTS   20000
#define N_C     64
#define N_B     2
#define N_P     2048
#define N_Q     (N_B * N_P)      // 4096
#define NS      32
#define R2      0.0064f          // 0.08^2
#define F1_OFF  8781824          // 2*67*2048*32 (start of idn region in d_out)

// Device scratch (no allocations allowed)
__device__ float g_ft[N_PTS * N_C];   // transposed features (N, C), 5.12 MB
__device__ float g_x2[N_PTS];         // per-point squared norm (reference rounding)
__device__ int   g_idx[N_Q * NS];
__device__ int   g_idn[N_Q * NS];

// ---------------------------------------------------------------------------
// Kernel 1a: per-point squared norm, matching reference rounding:
//   x2 = ((x*x + y*y) + z*z) with separately-rounded products (no fma)
// ---------------------------------------------------------------------------
__global__ void x2_kernel(const float* __restrict__ xyz) {
    int i = blockIdx.x * 256 + threadIdx.x;
    if (i < N_PTS) {
        float x = xyz[3 * i + 0];
        float y = xyz[3 * i + 1];
        float z = xyz[3 * i + 2];
        float s = __fadd_rn(__fadd_rn(__fmul_rn(x, x), __fmul_rn(y, y)),
                            __fmul_rn(z, z));
        g_x2[i] = s;
    }
}

// ---------------------------------------------------------------------------
// Kernel 1b: transpose features (C, N) -> (N, C) so the gather phase reads
// 256B contiguous per point instead of 64 scattered 4B loads (8x sector amp).
// N = 20000 = 625*32 exactly, C = 64 = 2*32 exactly -> no bounds checks.
// ---------------------------------------------------------------------------
__global__ void transpose_kernel(const float* __restrict__ feat) {
    __shared__ float t[32][33];
    int nb = blockIdx.x * 32;
    int cb = blockIdx.y * 32;
    int tx = threadIdx.x, ty = threadIdx.y;   // block (32, 8)
#pragma unroll
    for (int k = 0; k < 32; k += 8)
        t[ty + k][tx] = feat[(size_t)(cb + ty + k) * N_PTS + nb + tx];
    __syncthreads();
#pragma unroll
    for (int k = 0; k < 32; k += 8)
        g_ft[(size_t)(nb + ty + k) * N_C + cb + tx] = t[tx][ty + k];
}

// ---------------------------------------------------------------------------
// Kernel 2: ball query. One warp per query point, smem-tiled xyz scan in
// ascending point order. Each lane owns output slot 'lane' in a register;
// per-32-point chunk: ballot -> lanes in [cnt, cnt+popc) grab the
// (lane-cnt+1)-th set bit via __fns. Early exit once cnt >= 32.
//
// d2 replicates the reference exactly:
//   dot = fma(z,qz, fma(y,qy, x*qx))          (gemm-style fma chain)
//   d2  = fsub( fadd(q2, x2[n]), 2*dot )      (contraction blocked)
// ---------------------------------------------------------------------------
#define TILE 2560   // 80 chunks of 32; 4 arrays * 2560 * 4B = 40 KB smem

__global__ __launch_bounds__(256) void bq_kernel(const float* __restrict__ xyz,
                                                 const float* __restrict__ nxyz) {
    __shared__ float sx[TILE], sy[TILE], sz[TILE], s2[TILE];

    int tid  = threadIdx.x;
    int warp = tid >> 5;
    int lane = tid & 31;
    int qid  = blockIdx.x * 8 + warp;

    float qx = nxyz[3 * qid + 0];
    float qy = nxyz[3 * qid + 1];
    float qz = nxyz[3 * qid + 2];
    // q2 with reference rounding (mul,mul,mul,add,add)
    float q2 = __fadd_rn(__fadd_rn(__fmul_rn(qx, qx), __fmul_rn(qy, qy)),
                         __fmul_rn(qz, qz));

    int cnt   = 0;   // uniform across warp
    int myidx = 0;   // slot 'lane' of the result list

    for (int t0 = 0; t0 < N_PTS; t0 += TILE) {
        __syncthreads();
        // cooperative tile load (coalesced enough; xyz is (N,3) packed)
        for (int j = tid; j < TILE; j += 256) {
            int g = t0 + j;
            if (g < N_PTS) {
                sx[j] = xyz[3 * g + 0];
                sy[j] = xyz[3 * g + 1];
                sz[j] = xyz[3 * g + 2];
                s2[j] = g_x2[g];
            } else {
                sx[j] = 0.f; sy[j] = 0.f; sz[j] = 0.f;
                s2[j] = 1e30f;            // forces d2 >> R2 -> excluded
            }
        }
        __syncthreads();

        if (cnt < NS) {
#pragma unroll 4
            for (int c = 0; c < TILE / 32 && cnt < NS; c++) {
                int i = c * 32 + lane;
                float dot = __fmul_rn(sx[i], qx);
                dot = __fmaf_rn(sy[i], qy, dot);
                dot = __fmaf_rn(sz[i], qz, dot);
                float d2 = __fsub_rn(__fadd_rn(q2, s2[i]),
                                     __fmul_rn(2.0f, dot));
                unsigned mask = __ballot_sync(0xffffffffu, d2 < R2);
                if (mask) {
                    int pc = __popc(mask);
                    if (lane >= cnt) {
                        int need = lane - cnt + 1;     // 1-indexed
                        if (need <= pc)
                            myidx = t0 + c * 32 + (int)__fns(mask, 0, need);
                    }
                    cnt += pc;
                }
            }
        }
    }

    int firstIdx = __shfl_sync(0xffffffffu, myidx, 0);  // 0 if empty (myidx init)
    int outIdx, outIdn;
    if (cnt == 0) { outIdx = 0;  outIdn = 1; }
    else {
        int cc = cnt < NS ? cnt : NS;
        outIdx = (lane < cc) ? myidx : firstIdx;
        outIdn = (lane < cc) ? 1 : 0;
    }
    g_idx[qid * NS + lane] = outIdx;
    g_idn[qid * NS + lane] = outIdn;
}

// ---------------------------------------------------------------------------
// Kernel 3: grouping. One block (128 threads) per query.
// Stage 64 channels x 32 samples through padded smem:
//   - load g_ft[idx[s]*64 + c]: 2 coalesced 128B reads per sample
//   - write out[(b,3+ch,p,:)]: lanes = s, fully coalesced, conflict-free
// xyz-diff channels (0..2) and idn handled by warp 0 directly.
// ---------------------------------------------------------------------------
__global__ __launch_bounds__(128) void gather_kernel(const float* __restrict__ xyz,
                                                     const float* __restrict__ nxyz,
                                                     float* __restrict__ out) {
    __shared__ float sf[NS][65];   // pad 65 -> conflict-free [s][ch] reads
    __shared__ int   si[NS];
    __shared__ int   sd[NS];

    int q    = blockIdx.x;
    int b    = q >> 11;
    int p    = q & 2047;
    int tid  = threadIdx.x;
    int warp = tid >> 5;
    int lane = tid & 31;

    if (tid < NS) {
        si[tid] = g_idx[q * NS + tid];
        sd[tid] = g_idn[q * NS + tid];
    }
    __syncthreads();

#pragma unroll
    for (int s = warp; s < NS; s += 4) {
        int i = si[s];
        sf[s][lane]      = g_ft[(size_t)i * N_C + lane];
        sf[s][lane + 32] = g_ft[(size_t)i * N_C + 32 + lane];
    }
    __syncthreads();

    if (warp == 0) {
        int i = si[lane];
        float qx = nxyz[3 * q + 0];
        float qy = nxyz[3 * q + 1];
        float qz = nxyz[3 * q + 2];
        float ox = __fsub_rn(xyz[3 * i + 0], qx);
        float oy = __fsub_rn(xyz[3 * i + 1], qy);
        float oz = __fsub_rn(xyz[3 * i + 2], qz);
        size_t base = (((size_t)b * 67 + 0) * N_P + p) * NS + lane;
        size_t chs  = (size_t)N_P * NS;
        out[base]           = ox;
        out[base + chs]     = oy;
        out[base + 2 * chs] = oz;
        out[F1_OFF + (size_t)q * NS + lane] = (float)sd[lane];
    }

#pragma unroll
    for (int ch = warp; ch < N_C; ch += 4) {
        out[(((size_t)b * 67 + 3 + ch) * N_P + p) * NS + lane] = sf[lane][ch];
    }
}

// ---------------------------------------------------------------------------
extern "C" void kernel_launch(void* const* d_in, const int* in_sizes, int n_in,
                              void* d_out, int out_size) {
    const float* xyz  = (const float*)d_in[0];   // (20000, 3)
    const float* nxyz = (const float*)d_in[1];   // (2, 2048, 3)
    const float* feat = (const float*)d_in[2];   // (64, 20000)
    float* out = (float*)d_out;

    x2_kernel<<<(N_PTS + 255) / 256, 256>>>(xyz);
    transpose_kernel<<<dim3(N_PTS / 32, N_C / 32), dim3(32, 8)>>>(feat);
    bq_kernel<<<N_Q / 8, 256>>>(xyz, nxyz);
    gather_kernel<<<N_Q, 128>>>(xyz, nxyz, out);
}

// round 6
// speedup vs baseline: 2.2801x; 2.2801x over previous
#include <cuda_runtime.h>
#include <cuda_bf16.h>
#include <cstdint>

// Problem constants
#define N_PTS   20000
#define N_C     64
#define N_B     2
#define N_P     2048
#define N_Q     (N_B * N_P)      // 4096
#define NS      32
#define R2      0.0064f          // 0.08^2
#define F1_OFF  8781824          // 2*67*2048*32 (start of idn region in d_out)

// Grid constants: cell 1/12 = 0.08333 > radius 0.08 -> 27-neighborhood suffices
#define GD      12
#define NCELL   (GD * GD * GD)   // 1728
#define MAXC    256              // candidate cap per query (mean ~43)

// Device scratch (no allocations allowed)
__device__ float g_ft[N_PTS * N_C];   // transposed features (N, C)
__device__ int   g_idx[N_Q * NS];
__device__ int   g_idn[N_Q * NS];

__device__ int   g_cnt[NCELL];
__device__ int   g_fill[NCELL];
__device__ int   g_startc[NCELL + 1];
__device__ int   g_cell[N_PTS];
// cell-sorted point data (SoA)
__device__ float g_px[N_PTS], g_py[N_PTS], g_pz[N_PTS], g_px2[N_PTS];
__device__ int   g_pid[N_PTS];

// ---------------------------------------------------------------------------
// Grid build step 1: zero counters
// ---------------------------------------------------------------------------
__global__ void zero_kernel() {
    int i = blockIdx.x * 256 + threadIdx.x;
    if (i < NCELL) { g_cnt[i] = 0; g_fill[i] = 0; }
}

// ---------------------------------------------------------------------------
// Grid build step 2: count points per cell
// ---------------------------------------------------------------------------
__global__ void count_kernel(const float* __restrict__ xyz) {
    int i = blockIdx.x * 256 + threadIdx.x;
    if (i < N_PTS) {
        float x = xyz[3 * i + 0];
        float y = xyz[3 * i + 1];
        float z = xyz[3 * i + 2];
        int cx = min(GD - 1, max(0, (int)(x * (float)GD)));
        int cy = min(GD - 1, max(0, (int)(y * (float)GD)));
        int cz = min(GD - 1, max(0, (int)(z * (float)GD)));
        int c = (cz * GD + cy) * GD + cx;
        g_cell[i] = c;
        atomicAdd(&g_cnt[c], 1);
    }
}

// ---------------------------------------------------------------------------
// Grid build step 3: exclusive prefix scan of 1728 cell counts (one block)
// Hillis-Steele over 2048 with double buffer.
// ---------------------------------------------------------------------------
__global__ __launch_bounds__(1024) void scan_kernel() {
    __shared__ int a[2048], b[2048];
    int t = threadIdx.x;
    for (int i = t; i < 2048; i += 1024) a[i] = (i < NCELL) ? g_cnt[i] : 0;
    __syncthreads();
    int* src = a; int* dst = b;
    for (int off = 1; off < 2048; off <<= 1) {
        for (int i = t; i < 2048; i += 1024)
            dst[i] = (i >= off) ? (src[i] + src[i - off]) : src[i];
        __syncthreads();
        int* tmp = src; src = dst; dst = tmp;
    }
    // src = inclusive scan; emit exclusive with total at [NCELL]
    for (int i = t; i <= NCELL; i += 1024)
        g_startc[i] = (i == 0) ? 0 : src[i - 1];
}

// ---------------------------------------------------------------------------
// Grid build step 4: scatter points into cell-sorted SoA, with x2 computed
// using the reference rounding (mul,mul,mul,add,add -- no fma).
// ---------------------------------------------------------------------------
__global__ void scatter_kernel(const float* __restrict__ xyz) {
    int i = blockIdx.x * 256 + threadIdx.x;
    if (i < N_PTS) {
        float x = xyz[3 * i + 0];
        float y = xyz[3 * i + 1];
        float z = xyz[3 * i + 2];
        int c = g_cell[i];
        int pos = g_startc[c] + atomicAdd(&g_fill[c], 1);
        g_px[pos] = x; g_py[pos] = y; g_pz[pos] = z;
        g_px2[pos] = __fadd_rn(__fadd_rn(__fmul_rn(x, x), __fmul_rn(y, y)),
                               __fmul_rn(z, z));
        g_pid[pos] = i;
    }
}

// ---------------------------------------------------------------------------
// Transpose features (C, N) -> (N, C) for coalesced gather
// ---------------------------------------------------------------------------
__global__ void transpose_kernel(const float* __restrict__ feat) {
    __shared__ float t[32][33];
    int nb = blockIdx.x * 32;
    int cb = blockIdx.y * 32;
    int tx = threadIdx.x, ty = threadIdx.y;   // block (32, 8)
#pragma unroll
    for (int k = 0; k < 32; k += 8)
        t[ty + k][tx] = feat[(size_t)(cb + ty + k) * N_PTS + nb + tx];
    __syncthreads();
#pragma unroll
    for (int k = 0; k < 32; k += 8)
        g_ft[(size_t)(nb + ty + k) * N_C + cb + tx] = t[tx][ty + k];
}

// ---------------------------------------------------------------------------
// Grid ball query: one warp per query. Scan 3x3 rows of contiguous cells
// (x-neighbors are contiguous in the cell-sorted array), collect ALL in-ball
// candidates (unordered) into smem, bitonic-sort ascending by original index,
// take first 32. d2 rounding identical to the verified brute-force version.
// ---------------------------------------------------------------------------
__global__ __launch_bounds__(256) void bq_grid_kernel(const float* __restrict__ nxyz) {
    __shared__ int cand_s[8][MAXC];

    int tid  = threadIdx.x;
    int warp = tid >> 5;
    int lane = tid & 31;
    int qid  = blockIdx.x * 8 + warp;
    int* cand = cand_s[warp];
    unsigned lmask = (1u << lane) - 1u;

    float qx = nxyz[3 * qid + 0];
    float qy = nxyz[3 * qid + 1];
    float qz = nxyz[3 * qid + 2];
    float q2 = __fadd_rn(__fadd_rn(__fmul_rn(qx, qx), __fmul_rn(qy, qy)),
                         __fmul_rn(qz, qz));

    int qcx = min(GD - 1, max(0, (int)(qx * (float)GD)));
    int qcy = min(GD - 1, max(0, (int)(qy * (float)GD)));
    int qcz = min(GD - 1, max(0, (int)(qz * (float)GD)));
    int cx0 = max(0, qcx - 1), cx1 = min(GD - 1, qcx + 1);

    int cnt = 0;   // warp-uniform

#pragma unroll
    for (int dz = -1; dz <= 1; dz++) {
        int cz = qcz + dz;
        if (cz < 0 || cz >= GD) continue;
#pragma unroll
        for (int dy = -1; dy <= 1; dy++) {
            int cy = qcy + dy;
            if (cy < 0 || cy >= GD) continue;
            int base = (cz * GD + cy) * GD;
            int s0 = g_startc[base + cx0];
            int s1 = g_startc[base + cx1 + 1];
            for (int j0 = s0; j0 < s1; j0 += 32) {
                int j = j0 + lane;
                bool pred = false;
                int  pidv = 0;
                if (j < s1) {
                    float dot = __fmul_rn(g_px[j], qx);
                    dot = __fmaf_rn(g_py[j], qy, dot);
                    dot = __fmaf_rn(g_pz[j], qz, dot);
                    float d2 = __fsub_rn(__fadd_rn(q2, g_px2[j]),
                                         __fmul_rn(2.0f, dot));
                    if (d2 < R2) { pred = true; pidv = g_pid[j]; }
                }
                unsigned m = __ballot_sync(0xffffffffu, pred);
                if (m) {
                    if (pred) {
                        int pos = cnt + __popc(m & lmask);
                        if (pos < MAXC) cand[pos] = pidv;
                    }
                    cnt += __popc(m);
                }
            }
        }
    }
    if (cnt > MAXC) cnt = MAXC;

    int outIdx, outIdn;
    if (cnt == 0) {
        outIdx = 0; outIdn = 1;
    } else {
        int L = 32;
        while (L < cnt) L <<= 1;     // L in {32,64,128,256}
        for (int i = lane; i < L; i += 32)
            if (i >= cnt) cand[i] = 0x7fffffff;
        __syncwarp();
        for (int k = 2; k <= L; k <<= 1) {
            for (int j = k >> 1; j > 0; j >>= 1) {
                for (int i = lane; i < L; i += 32) {
                    int ixj = i ^ j;
                    if (ixj > i) {
                        int a = cand[i], b = cand[ixj];
                        bool asc = ((i & k) == 0);
                        if (asc ? (a > b) : (a < b)) {
                            cand[i] = b; cand[ixj] = a;
                        }
                    }
                }
                __syncwarp();
            }
        }
        int cc = cnt < NS ? cnt : NS;
        int first = cand[0];
        outIdx = (lane < cc) ? cand[lane] : first;
        outIdn = (lane < cc) ? 1 : 0;
    }
    g_idx[qid * NS + lane] = outIdx;
    g_idn[qid * NS + lane] = outIdn;
}

// ---------------------------------------------------------------------------
// Grouping: one block (128 threads) per query, smem-staged transpose.
// ---------------------------------------------------------------------------
__global__ __launch_bounds__(128) void gather_kernel(const float* __restrict__ xyz,
                                                     const float* __restrict__ nxyz,
                                                     float* __restrict__ out) {
    __shared__ float sf[NS][65];
    __shared__ int   si[NS];
    __shared__ int   sd[NS];

    int q    = blockIdx.x;
    int b    = q >> 11;
    int p    = q & 2047;
    int tid  = threadIdx.x;
    int warp = tid >> 5;
    int lane = tid & 31;

    if (tid < NS) {
        si[tid] = g_idx[q * NS + tid];
        sd[tid] = g_idn[q * NS + tid];
    }
    __syncthreads();

#pragma unroll
    for (int s = warp; s < NS; s += 4) {
        int i = si[s];
        sf[s][lane]      = g_ft[(size_t)i * N_C + lane];
        sf[s][lane + 32] = g_ft[(size_t)i * N_C + 32 + lane];
    }
    __syncthreads();

    if (warp == 0) {
        int i = si[lane];
        float qx = nxyz[3 * q + 0];
        float qy = nxyz[3 * q + 1];
        float qz = nxyz[3 * q + 2];
        float ox = __fsub_rn(xyz[3 * i + 0], qx);
        float oy = __fsub_rn(xyz[3 * i + 1], qy);
        float oz = __fsub_rn(xyz[3 * i + 2], qz);
        size_t base = (((size_t)b * 67 + 0) * N_P + p) * NS + lane;
        size_t chs  = (size_t)N_P * NS;
        out[base]           = ox;
        out[base + chs]     = oy;
        out[base + 2 * chs] = oz;
        out[F1_OFF + (size_t)q * NS + lane] = (float)sd[lane];
    }

#pragma unroll
    for (int ch = warp; ch < N_C; ch += 4) {
        out[(((size_t)b * 67 + 3 + ch) * N_P + p) * NS + lane] = sf[lane][ch];
    }
}

// ---------------------------------------------------------------------------
extern "C" void kernel_launch(void* const* d_in, const int* in_sizes, int n_in,
                              void* d_out, int out_size) {
    const float* xyz  = (const float*)d_in[0];   // (20000, 3)
    const float* nxyz = (const float*)d_in[1];   // (2, 2048, 3)
    const float* feat = (const float*)d_in[2];   // (64, 20000)
    float* out = (float*)d_out;

    zero_kernel<<<(NCELL + 255) / 256, 256>>>();
    count_kernel<<<(N_PTS + 255) / 256, 256>>>(xyz);
    scan_kernel<<<1, 1024>>>();
    scatter_kernel<<<(N_PTS + 255) / 256, 256>>>(xyz);
    transpose_kernel<<<dim3(N_PTS / 32, N_C / 32), dim3(32, 8)>>>(feat);
    bq_grid_kernel<<<N_Q / 8, 256>>>(nxyz);
    gather_kernel<<<N_Q, 128>>>(xyz, nxyz, out);
}

// round 7
// speedup vs baseline: 2.3657x; 1.0375x over previous
#include <cuda_runtime.h>
#include <cuda_bf16.h>
#include <cstdint>

// Problem constants
#define N_PTS   20000
#define N_C     64
#define N_B     2
#define N_P     2048
#define N_Q     (N_B * N_P)      // 4096
#define NS      32
#define R2      0.0064f          // 0.08^2
#define F1_OFF  8781824          // 2*67*2048*32 (start of idn region in d_out)

// Grid constants: cell 1/12 = 0.08333 > radius 0.08 -> 27-neighborhood suffices
#define GD      12
#define NCELL   (GD * GD * GD)   // 1728
#define MAXC    256              // candidate cap per query (mean ~43)

// Device scratch (no allocations allowed)
__device__ float g_ft[N_PTS * N_C];   // transposed features (N, C)
__device__ int   g_idx[N_Q * NS];
__device__ int   g_idn[N_Q * NS];

__device__ int   g_cnt[NCELL];        // zero at module load; re-zeroed by scan_kernel
__device__ int   g_startc[NCELL + 1];
__device__ int   g_cellrank[N_PTS];   // (cell << 13) | rank-within-cell
// cell-sorted point data (SoA)
__device__ float g_px[N_PTS], g_py[N_PTS], g_pz[N_PTS], g_px2[N_PTS];
__device__ int   g_pid[N_PTS];

// ---------------------------------------------------------------------------
// Grid build step 1: count points per cell; the atomic's return value IS the
// within-cell rank, so scatter needs no atomics. Pack cell+rank in one int.
// ---------------------------------------------------------------------------
__global__ void count_kernel(const float* __restrict__ xyz) {
    int i = blockIdx.x * 256 + threadIdx.x;
    if (i < N_PTS) {
        float x = xyz[3 * i + 0];
        float y = xyz[3 * i + 1];
        float z = xyz[3 * i + 2];
        int cx = min(GD - 1, max(0, (int)(x * (float)GD)));
        int cy = min(GD - 1, max(0, (int)(y * (float)GD)));
        int cz = min(GD - 1, max(0, (int)(z * (float)GD)));
        int c = (cz * GD + cy) * GD + cx;
        int r = atomicAdd(&g_cnt[c], 1);
        g_cellrank[i] = (c << 13) | r;
    }
}

// ---------------------------------------------------------------------------
// Grid build step 2: exclusive prefix scan of 1728 cell counts (one block),
// then re-zero g_cnt so the next graph replay starts clean (no zero kernel).
// ---------------------------------------------------------------------------
__global__ __launch_bounds__(1024) void scan_kernel() {
    __shared__ int a[2048], b[2048];
    int t = threadIdx.x;
    for (int i = t; i < 2048; i += 1024) a[i] = (i < NCELL) ? g_cnt[i] : 0;
    __syncthreads();
    int* src = a; int* dst = b;
    for (int off = 1; off < 2048; off <<= 1) {
        for (int i = t; i < 2048; i += 1024)
            dst[i] = (i >= off) ? (src[i] + src[i - off]) : src[i];
        __syncthreads();
        int* tmp = src; src = dst; dst = tmp;
    }
    // src = inclusive scan; emit exclusive with total at [NCELL]
    for (int i = t; i <= NCELL; i += 1024)
        g_startc[i] = (i == 0) ? 0 : src[i - 1];
    for (int i = t; i < NCELL; i += 1024)
        g_cnt[i] = 0;
}

// ---------------------------------------------------------------------------
// Grid build step 3: atomic-free scatter into cell-sorted SoA, x2 with the
// reference rounding (mul,mul,mul,add,add -- no fma).
// ---------------------------------------------------------------------------
__global__ void scatter_kernel(const float* __restrict__ xyz) {
    int i = blockIdx.x * 256 + threadIdx.x;
    if (i < N_PTS) {
        float x = xyz[3 * i + 0];
        float y = xyz[3 * i + 1];
        float z = xyz[3 * i + 2];
        int pr  = g_cellrank[i];
        int pos = g_startc[pr >> 13] + (pr & 8191);
        g_px[pos] = x; g_py[pos] = y; g_pz[pos] = z;
        g_px2[pos] = __fadd_rn(__fadd_rn(__fmul_rn(x, x), __fmul_rn(y, y)),
                               __fmul_rn(z, z));
        g_pid[pos] = i;
    }
}

// ---------------------------------------------------------------------------
// Transpose features (C, N) -> (N, C) for coalesced gather
// ---------------------------------------------------------------------------
__global__ void transpose_kernel(const float* __restrict__ feat) {
    __shared__ float t[32][33];
    int nb = blockIdx.x * 32;
    int cb = blockIdx.y * 32;
    int tx = threadIdx.x, ty = threadIdx.y;   // block (32, 8)
#pragma unroll
    for (int k = 0; k < 32; k += 8)
        t[ty + k][tx] = feat[(size_t)(cb + ty + k) * N_PTS + nb + tx];
    __syncthreads();
#pragma unroll
    for (int k = 0; k < 32; k += 8)
        g_ft[(size_t)(nb + ty + k) * N_C + cb + tx] = t[tx][ty + k];
}

// ---------------------------------------------------------------------------
// Grid ball query: one warp per query. Scan 3x3 rows of contiguous cells
// (x-neighbors are contiguous in the cell-sorted array), collect ALL in-ball
// candidates (unordered) into smem, bitonic-sort ascending by original index,
// take first 32. d2 rounding identical to the verified brute-force version.
// ---------------------------------------------------------------------------
__global__ __launch_bounds__(256) void bq_grid_kernel(const float* __restrict__ nxyz) {
    __shared__ int cand_s[8][MAXC];

    int tid  = threadIdx.x;
    int warp = tid >> 5;
    int lane = tid & 31;
    int qid  = blockIdx.x * 8 + warp;
    int* cand = cand_s[warp];
    unsigned lmask = (1u << lane) - 1u;

    float qx = nxyz[3 * qid + 0];
    float qy = nxyz[3 * qid + 1];
    float qz = nxyz[3 * qid + 2];
    float q2 = __fadd_rn(__fadd_rn(__fmul_rn(qx, qx), __fmul_rn(qy, qy)),
                         __fmul_rn(qz, qz));

    int qcx = min(GD - 1, max(0, (int)(qx * (float)GD)));
    int qcy = min(GD - 1, max(0, (int)(qy * (float)GD)));
    int qcz = min(GD - 1, max(0, (int)(qz * (float)GD)));
    int cx0 = max(0, qcx - 1), cx1 = min(GD - 1, qcx + 1);

    int cnt = 0;   // warp-uniform

#pragma unroll
    for (int dz = -1; dz <= 1; dz++) {
        int cz = qcz + dz;
        if (cz < 0 || cz >= GD) continue;
#pragma unroll
        for (int dy = -1; dy <= 1; dy++) {
            int cy = qcy + dy;
            if (cy < 0 || cy >= GD) continue;
            int base = (cz * GD + cy) * GD;
            int s0 = g_startc[base + cx0];
            int s1 = g_startc[base + cx1 + 1];
            for (int j0 = s0; j0 < s1; j0 += 32) {
                int j = j0 + lane;
                bool pred = false;
                int  pidv = 0;
                if (j < s1) {
                    float dot = __fmul_rn(g_px[j], qx);
                    dot = __fmaf_rn(g_py[j], qy, dot);
                    dot = __fmaf_rn(g_pz[j], qz, dot);
                    float d2 = __fsub_rn(__fadd_rn(q2, g_px2[j]),
                                         __fmul_rn(2.0f, dot));
                    if (d2 < R2) { pred = true; pidv = g_pid[j]; }
                }
                unsigned m = __ballot_sync(0xffffffffu, pred);
                if (m) {
                    if (pred) {
                        int pos = cnt + __popc(m & lmask);
                        if (pos < MAXC) cand[pos] = pidv;
                    }
                    cnt += __popc(m);
                }
            }
        }
    }
    if (cnt > MAXC) cnt = MAXC;

    int outIdx, outIdn;
    if (cnt == 0) {
        outIdx = 0; outIdn = 1;
    } else {
        int L = 32;
        while (L < cnt) L <<= 1;     // L in {32,64,128,256}
        for (int i = lane; i < L; i += 32)
            if (i >= cnt) cand[i] = 0x7fffffff;
        __syncwarp();
        for (int k = 2; k <= L; k <<= 1) {
            for (int j = k >> 1; j > 0; j >>= 1) {
                for (int i = lane; i < L; i += 32) {
                    int ixj = i ^ j;
                    if (ixj > i) {
                        int a = cand[i], b = cand[ixj];
                        bool asc = ((i & k) == 0);
                        if (asc ? (a > b) : (a < b)) {
                            cand[i] = b; cand[ixj] = a;
                        }
                    }
                }
                __syncwarp();
            }
        }
        int cc = cnt < NS ? cnt : NS;
        int first = cand[0];
        outIdx = (lane < cc) ? cand[lane] : first;
        outIdn = (lane < cc) ? 1 : 0;
    }
    g_idx[qid * NS + lane] = outIdx;
    g_idn[qid * NS + lane] = outIdn;
}

// ---------------------------------------------------------------------------
// Grouping: one block (128 threads) per query. float4 loads from g_ft into a
// stride-65 smem tile, then float4 stores per channel row. Store-phase lane
// map (csub*8+sg) makes the 4 scalar LDS per float4 bank-conflict-free:
// bank = (65*(4sg+k)+ch) mod 32 = (4sg + k + ch) mod 32 -> 32 distinct lanes.
// ---------------------------------------------------------------------------
__global__ __launch_bounds__(128) void gather_kernel(const float* __restrict__ xyz,
                                                     const float* __restrict__ nxyz,
                                                     float* __restrict__ out) {
    __shared__ float sf[NS * 65];
    __shared__ int   si[NS];
    __shared__ int   sd[NS];

    int q    = blockIdx.x;
    int b    = q >> 11;
    int p    = q & 2047;
    int tid  = threadIdx.x;
    int warp = tid >> 5;
    int lane = tid & 31;

    if (tid < NS) {
        si[tid] = g_idx[q * NS + tid];
        sd[tid] = g_idn[q * NS + tid];
    }
    __syncthreads();

    // Load phase: each warp loads 2 feature rows per iter (16 float4 per row).
    {
        int q4   = lane & 15;     // float4 index within the 64-float row
        int ssub = lane >> 4;     // 0..1
#pragma unroll
        for (int it = 0; it < 4; it++) {
            int s = it * 8 + warp * 2 + ssub;
            int i = si[s];
            float4 v = *(const float4*)(g_ft + (size_t)i * N_C + q4 * 4);
            float* dst = sf + s * 65 + q4 * 4;
            dst[0] = v.x; dst[1] = v.y; dst[2] = v.z; dst[3] = v.w;
        }
    }
    __syncthreads();

    if (warp == 0) {
        int i = si[lane];
        float qx = nxyz[3 * q + 0];
        float qy = nxyz[3 * q + 1];
        float qz = nxyz[3 * q + 2];
        float ox = __fsub_rn(xyz[3 * i + 0], qx);
        float oy = __fsub_rn(xyz[3 * i + 1], qy);
        float oz = __fsub_rn(xyz[3 * i + 2], qz);
        size_t base = (((size_t)b * 67 + 0) * N_P + p) * NS + lane;
        size_t chs  = (size_t)N_P * NS;
        out[base]           = ox;
        out[base + chs]     = oy;
        out[base + 2 * chs] = oz;
        out[F1_OFF + (size_t)q * NS + lane] = (float)sd[lane];
    }

    // Store phase: 64 feature channels as float4 rows (8 stores per channel).
    {
        int sg   = lane & 7;      // sample group: samples 4*sg .. 4*sg+3
        int csub = lane >> 3;     // 0..3
#pragma unroll
        for (int it = 0; it < 4; it++) {
            int ch = it * 16 + warp * 4 + csub;
            float4 v;
            v.x = sf[(4 * sg + 0) * 65 + ch];
            v.y = sf[(4 * sg + 1) * 65 + ch];
            v.z = sf[(4 * sg + 2) * 65 + ch];
            v.w = sf[(4 * sg + 3) * 65 + ch];
            *(float4*)(out + (((size_t)b * 67 + 3 + ch) * N_P + p) * NS + 4 * sg) = v;
        }
    }
}

// ---------------------------------------------------------------------------
extern "C" void kernel_launch(void* const* d_in, const int* in_sizes, int n_in,
                              void* d_out, int out_size) {
    const float* xyz  = (const float*)d_in[0];   // (20000, 3)
    const float* nxyz = (const float*)d_in[1];   // (2, 2048, 3)
    const float* feat = (const float*)d_in[2];   // (64, 20000)
    float* out = (float*)d_out;

    count_kernel<<<(N_PTS + 255) / 256, 256>>>(xyz);
    scan_kernel<<<1, 1024>>>();
    scatter_kernel<<<(N_PTS + 255) / 256, 256>>>(xyz);
    transpose_kernel<<<dim3(N_PTS / 32, N_C / 32), dim3(32, 8)>>>(feat);
    bq_grid_kernel<<<N_Q / 8, 256>>>(nxyz);
    gather_kernel<<<N_Q, 128>>>(xyz, nxyz, out);
}

// round 9
// speedup vs baseline: 2.5058x; 1.0592x over previous
#include <cuda_runtime.h>
#include <cuda_bf16.h>
#include <cstdint>

// Problem constants
#define N_PTS   20000
#define N_C     64
#define N_B     2
#define N_P     2048
#define N_Q     (N_B * N_P)      // 4096
#define NS      32
#define R2      0.0064f          // 0.08^2
#define F1_OFF  8781824          // 2*67*2048*32 (start of idn region in d_out)

// Grid constants: cell 1/12 = 0.08333 > radius 0.08 -> 27-neighborhood suffices
#define GD      12
#define NCELL   (GD * GD * GD)   // 1728
#define MAXC    256              // candidate cap per query (mean ~43)

#define BQ_BLOCKS (N_Q / 8)      // 512
#define TR_BLOCKS 1250           // 625 N-tiles x 2 C-tiles (32x32 each)

// Device scratch (no allocations allowed)
__device__ float g_ft[N_PTS * N_C];   // transposed features (N, C)
__device__ int   g_idx[N_Q * NS];
__device__ int   g_idn[N_Q * NS];

__device__ int   g_cnt[NCELL];        // zero at module load; re-zeroed by scan_kernel
__device__ int   g_startc[NCELL + 1];
__device__ int   g_cellrank[N_PTS];   // (cell << 13) | rank-within-cell
// cell-sorted point data (SoA)
__device__ float g_px[N_PTS], g_py[N_PTS], g_pz[N_PTS], g_px2[N_PTS];
__device__ int   g_pid[N_PTS];

// ---------------------------------------------------------------------------
// Step 1: count points per cell; atomic return value IS the within-cell rank.
// ---------------------------------------------------------------------------
__global__ void count_kernel(const float* __restrict__ xyz) {
    int i = blockIdx.x * 256 + threadIdx.x;
    if (i < N_PTS) {
        float x = xyz[3 * i + 0];
        float y = xyz[3 * i + 1];
        float z = xyz[3 * i + 2];
        int cx = min(GD - 1, max(0, (int)(x * (float)GD)));
        int cy = min(GD - 1, max(0, (int)(y * (float)GD)));
        int cz = min(GD - 1, max(0, (int)(z * (float)GD)));
        int c = (cz * GD + cy) * GD + cx;
        int r = atomicAdd(&g_cnt[c], 1);
        g_cellrank[i] = (c << 13) | r;
    }
}

// ---------------------------------------------------------------------------
// Step 2: exclusive scan of 1728 cell counts via shfl warp-scan (2 barriers),
// then re-zero g_cnt for the next graph replay.
// ---------------------------------------------------------------------------
__global__ __launch_bounds__(1024) void scan_kernel() {
    __shared__ int wsum[32];
    int t = threadIdx.x;
    int lane = t & 31, w = t >> 5;

    int e0 = 0, e1 = 0;
    if (2 * t < NCELL)     e0 = g_cnt[2 * t];
    if (2 * t + 1 < NCELL) e1 = g_cnt[2 * t + 1];
    int s = e0 + e1;

    int inc = s;
#pragma unroll
    for (int o = 1; o < 32; o <<= 1) {
        int v = __shfl_up_sync(0xffffffffu, inc, o);
        if (lane >= o) inc += v;
    }
    if (lane == 31) wsum[w] = inc;
    __syncthreads();
    if (w == 0) {
        int v = wsum[lane];
        int iv = v;
#pragma unroll
        for (int o = 1; o < 32; o <<= 1) {
            int u = __shfl_up_sync(0xffffffffu, iv, o);
            if (lane >= o) iv += u;
        }
        wsum[lane] = iv - v;      // exclusive warp offsets
    }
    __syncthreads();

    int excl = inc - s + wsum[w];
    if (2 * t < NCELL) {
        g_startc[2 * t] = excl;
        g_cnt[2 * t] = 0;
    }
    if (2 * t + 1 < NCELL) {
        g_startc[2 * t + 1] = excl + e0;
        g_cnt[2 * t + 1] = 0;
    }
    if (2 * t + 1 == NCELL - 1)
        g_startc[NCELL] = excl + e0 + e1;
}

// ---------------------------------------------------------------------------
// Step 3: atomic-free scatter into cell-sorted SoA, x2 with reference
// rounding (mul,mul,mul,add,add -- no fma).
// ---------------------------------------------------------------------------
__global__ void scatter_kernel(const float* __restrict__ xyz) {
    int i = blockIdx.x * 256 + threadIdx.x;
    if (i < N_PTS) {
        float x = xyz[3 * i + 0];
        float y = xyz[3 * i + 1];
        float z = xyz[3 * i + 2];
        int pr  = g_cellrank[i];
        int pos = g_startc[pr >> 13] + (pr & 8191);
        g_px[pos] = x; g_py[pos] = y; g_pz[pos] = z;
        g_px2[pos] = __fadd_rn(__fadd_rn(__fmul_rn(x, x), __fmul_rn(y, y)),
                               __fmul_rn(z, z));
        g_pid[pos] = i;
    }
}

// ---------------------------------------------------------------------------
// Step 4 (fused): grid ball query (blocks [0, 512)) + feature transpose
// (blocks [512, 512+1250)). Transpose is independent of the grid build and
// only gates the gather kernel, so it hides under bq's latency-bound warps.
//
// Transpose: 32(N) x 32(C) tile, float4 on both global sides, stride-33 smem.
//   STS banks: (33*(4*n4+k)+cidx) % 32 = (4*n4+k+cidx) % 32 -> conflict-free.
//   LDS banks: (33*nidx+4*c4+k) % 32 = (nidx+4*c4+k) % 32   -> conflict-free.
//
// BQ: one warp per query, 3x3 contiguous cell rows, collect all in-ball
// candidates, bitonic sort ascending by original index, take first 32.
// d2 rounding identical to the verified brute-force version.
// ---------------------------------------------------------------------------
__global__ __launch_bounds__(256) void bq_tr_kernel(const float* __restrict__ nxyz,
                                                    const float* __restrict__ feat) {
    if (blockIdx.x >= BQ_BLOCKS) {
        // ---- transpose branch ----
        __shared__ float st[32 * 33];
        int tb  = blockIdx.x - BQ_BLOCKS;
        int nb  = (tb >> 1) * 32;
        int cb  = (tb & 1) * 32;
        int tid = threadIdx.x;

        int cidx = tid >> 3, n4 = tid & 7;
        float4 v = *(const float4*)(feat + (size_t)(cb + cidx) * N_PTS + nb + 4 * n4);
        st[(4 * n4 + 0) * 33 + cidx] = v.x;
        st[(4 * n4 + 1) * 33 + cidx] = v.y;
        st[(4 * n4 + 2) * 33 + cidx] = v.z;
        st[(4 * n4 + 3) * 33 + cidx] = v.w;
        __syncthreads();

        int nidx = tid >> 3, c4 = tid & 7;
        float4 w;
        w.x = st[nidx * 33 + 4 * c4 + 0];
        w.y = st[nidx * 33 + 4 * c4 + 1];
        w.z = st[nidx * 33 + 4 * c4 + 2];
        w.w = st[nidx * 33 + 4 * c4 + 3];
        *(float4*)(g_ft + (size_t)(nb + nidx) * N_C + cb + 4 * c4) = w;
        return;
    }

    // ---- ball-query branch ----
    __shared__ int cand_s[8][MAXC];

    int tid  = threadIdx.x;
    int warp = tid >> 5;
    int lane = tid & 31;
    int qid  = blockIdx.x * 8 + warp;
    int* cand = cand_s[warp];
    unsigned lmask = (1u << lane) - 1u;

    float qx = nxyz[3 * qid + 0];
    float qy = nxyz[3 * qid + 1];
    float qz = nxyz[3 * qid + 2];
    float q2 = __fadd_rn(__fadd_rn(__fmul_rn(qx, qx), __fmul_rn(qy, qy)),
                         __fmul_rn(qz, qz));

    int qcx = min(GD - 1, max(0, (int)(qx * (float)GD)));
    int qcy = min(GD - 1, max(0, (int)(qy * (float)GD)));
    int qcz = min(GD - 1, max(0, (int)(qz * (float)GD)));
    int cx0 = max(0, qcx - 1), cx1 = min(GD - 1, qcx + 1);

    int cnt = 0;   // warp-uniform

#pragma unroll
    for (int dz = -1; dz <= 1; dz++) {
        int cz = qcz + dz;
        if (cz < 0 || cz >= GD) continue;
#pragma unroll
        for (int dy = -1; dy <= 1; dy++) {
            int cy = qcy + dy;
            if (cy < 0 || cy >= GD) continue;
            int base = (cz * GD + cy) * GD;
            int s0 = g_startc[base + cx0];
            int s1 = g_startc[base + cx1 + 1];
            for (int j0 = s0; j0 < s1; j0 += 32) {
                int j = j0 + lane;
                bool pred = false;
                int  pidv = 0;
                if (j < s1) {
                    float dot = __fmul_rn(g_px[j], qx);
                    dot = __fmaf_rn(g_py[j], qy, dot);
                    dot = __fmaf_rn(g_pz[j], qz, dot);
                    float d2 = __fsub_rn(__fadd_rn(q2, g_px2[j]),
                                         __fmul_rn(2.0f, dot));
                    if (d2 < R2) { pred = true; pidv = g_pid[j]; }
                }
                unsigned m = __ballot_sync(0xffffffffu, pred);
                if (m) {
                    if (pred) {
                        int pos = cnt + __popc(m & lmask);
                        if (pos < MAXC) cand[pos] = pidv;
                    }
                    cnt += __popc(m);
                }
            }
        }
    }
    if (cnt > MAXC) cnt = MAXC;

    int outIdx, outIdn;
    if (cnt == 0) {
        outIdx = 0; outIdn = 1;
    } else {
        int L = 32;
        while (L < cnt) L <<= 1;     // L in {32,64,128,256}
        for (int i = lane; i < L; i += 32)
            if (i >= cnt) cand[i] = 0x7fffffff;
        __syncwarp();
        for (int k = 2; k <= L; k <<= 1) {
            for (int j = k >> 1; j > 0; j >>= 1) {
                for (int i = lane; i < L; i += 32) {
                    int ixj = i ^ j;
                    if (ixj > i) {
                        int a = cand[i], b = cand[ixj];
                        bool asc = ((i & k) == 0);
                        if (asc ? (a > b) : (a < b)) {
                            cand[i] = b; cand[ixj] = a;
                        }
                    }
                }
                __syncwarp();
            }
        }
        int cc = cnt < NS ? cnt : NS;
        int first = cand[0];
        outIdx = (lane < cc) ? cand[lane] : first;
        outIdn = (lane < cc) ? 1 : 0;
    }
    g_idx[qid * NS + lane] = outIdx;
    g_idn[qid * NS + lane] = outIdn;
}

// ---------------------------------------------------------------------------
// Grouping: one block (128 threads) per query. float4 loads from g_ft into a
// stride-65 smem tile, then float4 stores per channel row (bank-conflict-free
// lane maps, verified round 7).
// ---------------------------------------------------------------------------
__global__ __launch_bounds__(128) void gather_kernel(const float* __restrict__ xyz,
                                                     const float* __restrict__ nxyz,
                                                     float* __restrict__ out) {
    __shared__ float sf[NS * 65];
    __shared__ int   si[NS];
    __shared__ int   sd[NS];

    int q    = blockIdx.x;
    int b    = q >> 11;
    int p    = q & 2047;
    int tid  = threadIdx.x;
    int warp = tid >> 5;
    int lane = tid & 31;

    if (tid < NS) {
        si[tid] = g_idx[q * NS + tid];
        sd[tid] = g_idn[q * NS + tid];
    }
    __syncthreads();

    // Load phase: each warp loads 2 feature rows per iter (16 float4 per row).
    {
        int q4   = lane & 15;
        int ssub = lane >> 4;
#pragma unroll
        for (int it = 0; it < 4; it++) {
            int s = it * 8 + warp * 2 + ssub;
            int i = si[s];
            float4 v = *(const float4*)(g_ft + (size_t)i * N_C + q4 * 4);
            float* dst = sf + s * 65 + q4 * 4;
            dst[0] = v.x; dst[1] = v.y; dst[2] = v.z; dst[3] = v.w;
        }
    }
    __syncthreads();

    if (warp == 0) {
        int i = si[lane];
        float qx = nxyz[3 * q + 0];
        float qy = nxyz[3 * q + 1];
        float qz = nxyz[3 * q + 2];
        float ox = __fsub_rn(xyz[3 * i + 0], qx);
        float oy = __fsub_rn(xyz[3 * i + 1], qy);
        float oz = __fsub_rn(xyz[3 * i + 2], qz);
        size_t base = (((size_t)b * 67 + 0) * N_P + p) * NS + lane;
        size_t chs  = (size_t)N_P * NS;
        out[base]           = ox;
        out[base + chs]     = oy;
        out[base + 2 * chs] = oz;
        out[F1_OFF + (size_t)q * NS + lane] = (float)sd[lane];
    }

    // Store phase: 64 feature channels as float4 rows (8 stores per channel).
    {
        int sg   = lane & 7;
        int csub = lane >> 3;
#pragma unroll
        for (int it = 0; it < 4; it++) {
            int ch = it * 16 + warp * 4 + csub;
            float4 v;
            v.x = sf[(4 * sg + 0) * 65 + ch];
            v.y = sf[(4 * sg + 1) * 65 + ch];
            v.z = sf[(4 * sg + 2) * 65 + ch];
            v.w = sf[(4 * sg + 3) * 65 + ch];
            *(float4*)(out + (((size_t)b * 67 + 3 + ch) * N_P + p) * NS + 4 * sg) = v;
        }
    }
}

// ---------------------------------------------------------------------------
extern "C" void kernel_launch(void* const* d_in, const int* in_sizes, int n_in,
                              void* d_out, int out_size) {
    const float* xyz  = (const float*)d_in[0];   // (20000, 3)
    const float* nxyz = (const float*)d_in[1];   // (2, 2048, 3)
    const float* feat = (const float*)d_in[2];   // (64, 20000)
    float* out = (float*)d_out;

    count_kernel<<<(N_PTS + 255) / 256, 256>>>(xyz);
    scan_kernel<<<1, 1024>>>();
    scatter_kernel<<<(N_PTS + 255) / 256, 256>>>(xyz);
    bq_tr_kernel<<<BQ_BLOCKS + TR_BLOCKS, 256>>>(nxyz, feat);
    gather_kernel<<<N_Q, 128>>>(xyz, nxyz, out);
}

// round 11
// speedup vs baseline: 3.2974x; 1.3159x over previous
#include <cuda_runtime.h>
#include <cuda_bf16.h>
#include <cstdint>

// Problem constants
#define N_PTS   20000
#define N_C     64
#define N_B     2
#define N_P     2048
#define N_Q     (N_B * N_P)      // 4096
#define NS      32
#define R2      0.0064f          // 0.08^2
#define R2PAD   0.00641f         // R2 + 1e-5 margin: covers fp noise of ref d2
#define CW      (1.0f / 12.0f)   // cell width
#define F1_OFF  8781824          // 2*67*2048*32 (start of idn region in d_out)

// Grid constants: cell 1/12 = 0.08333 > radius 0.08 -> 27-neighborhood suffices
#define GD      12
#define NCELL   (GD * GD * GD)   // 1728
#define MAXC    256              // candidate cap per query (mean ~43)

#define CNT_BLOCKS 79            // ceil(20000/256)
#define TR_BLOCKS  1250          // 625 N-tiles x 2 C-tiles (32x32 each)

// Device scratch (no allocations allowed)
__device__ float  g_ft[N_PTS * N_C];  // transposed features (N, C)
__device__ int    g_idx[N_Q * NS];
__device__ int    g_idn[N_Q * NS];

__device__ int    g_cnt[NCELL];       // zero at module load; re-zeroed by scan_kernel
__device__ int    g_startc[NCELL + 1];
__device__ int    g_cellrank[N_PTS];  // (cell << 13) | rank-within-cell
// cell-sorted point data: (x, y, z, x2) packed for one LDG.128 per candidate
__device__ float4 g_pts[N_PTS];
__device__ int    g_pid[N_PTS];

// ---------------------------------------------------------------------------
// Step 1 (fused): count points per cell (blocks < CNT_BLOCKS) + feature
// transpose (remaining blocks). Both are independent heads of the dep chain.
// Count: atomic return value IS the within-cell rank -> scatter is atomic-free.
// Transpose: 32x32 tile, float4 both global sides, stride-33 smem
// (conflict-free both phases; verified round 7).
// ---------------------------------------------------------------------------
__global__ __launch_bounds__(256) void count_tr_kernel(const float* __restrict__ xyz,
                                                       const float* __restrict__ feat) {
    if (blockIdx.x >= CNT_BLOCKS) {
        __shared__ float st[32 * 33];
        int tb  = blockIdx.x - CNT_BLOCKS;
        int nb  = (tb >> 1) * 32;
        int cb  = (tb & 1) * 32;
        int tid = threadIdx.x;

        int cidx = tid >> 3, n4 = tid & 7;
        float4 v = *(const float4*)(feat + (size_t)(cb + cidx) * N_PTS + nb + 4 * n4);
        st[(4 * n4 + 0) * 33 + cidx] = v.x;
        st[(4 * n4 + 1) * 33 + cidx] = v.y;
        st[(4 * n4 + 2) * 33 + cidx] = v.z;
        st[(4 * n4 + 3) * 33 + cidx] = v.w;
        __syncthreads();

        int nidx = tid >> 3, c4 = tid & 7;
        float4 w;
        w.x = st[nidx * 33 + 4 * c4 + 0];
        w.y = st[nidx * 33 + 4 * c4 + 1];
        w.z = st[nidx * 33 + 4 * c4 + 2];
        w.w = st[nidx * 33 + 4 * c4 + 3];
        *(float4*)(g_ft + (size_t)(nb + nidx) * N_C + cb + 4 * c4) = w;
        return;
    }

    int i = blockIdx.x * 256 + threadIdx.x;
    if (i < N_PTS) {
        float x = xyz[3 * i + 0];
        float y = xyz[3 * i + 1];
        float z = xyz[3 * i + 2];
        int cx = min(GD - 1, max(0, (int)(x * (float)GD)));
        int cy = min(GD - 1, max(0, (int)(y * (float)GD)));
        int cz = min(GD - 1, max(0, (int)(z * (float)GD)));
        int c = (cz * GD + cy) * GD + cx;
        int r = atomicAdd(&g_cnt[c], 1);
        g_cellrank[i] = (c << 13) | r;
    }
}

// ---------------------------------------------------------------------------
// Step 2: exclusive scan of 1728 cell counts via shfl warp-scan (2 barriers),
// then re-zero g_cnt for the next graph replay.
// ---------------------------------------------------------------------------
__global__ __launch_bounds__(1024) void scan_kernel() {
    __shared__ int wsum[32];
    int t = threadIdx.x;
    int lane = t & 31, w = t >> 5;

    int e0 = 0, e1 = 0;
    if (2 * t < NCELL)     e0 = g_cnt[2 * t];
    if (2 * t + 1 < NCELL) e1 = g_cnt[2 * t + 1];
    int s = e0 + e1;

    int inc = s;
#pragma unroll
    for (int o = 1; o < 32; o <<= 1) {
        int v = __shfl_up_sync(0xffffffffu, inc, o);
        if (lane >= o) inc += v;
    }
    if (lane == 31) wsum[w] = inc;
    __syncthreads();
    if (w == 0) {
        int v = wsum[lane];
        int iv = v;
#pragma unroll
        for (int o = 1; o < 32; o <<= 1) {
            int u = __shfl_up_sync(0xffffffffu, iv, o);
            if (lane >= o) iv += u;
        }
        wsum[lane] = iv - v;      // exclusive warp offsets
    }
    __syncthreads();

    int excl = inc - s + wsum[w];
    if (2 * t < NCELL) {
        g_startc[2 * t] = excl;
        g_cnt[2 * t] = 0;
    }
    if (2 * t + 1 < NCELL) {
        g_startc[2 * t + 1] = excl + e0;
        g_cnt[2 * t + 1] = 0;
    }
    if (2 * t + 1 == NCELL - 1)
        g_startc[NCELL] = excl + e0 + e1;
}

// ---------------------------------------------------------------------------
// Step 3: atomic-free scatter into cell-sorted float4 SoA; x2 with reference
// rounding (mul,mul,mul,add,add -- no fma).
// ---------------------------------------------------------------------------
__global__ void scatter_kernel(const float* __restrict__ xyz) {
    int i = blockIdx.x * 256 + threadIdx.x;
    if (i < N_PTS) {
        float x = xyz[3 * i + 0];
        float y = xyz[3 * i + 1];
        float z = xyz[3 * i + 2];
        int pr  = g_cellrank[i];
        int pos = g_startc[pr >> 13] + (pr & 8191);
        float x2 = __fadd_rn(__fadd_rn(__fmul_rn(x, x), __fmul_rn(y, y)),
                             __fmul_rn(z, z));
        g_pts[pos] = make_float4(x, y, z, x2);
        g_pid[pos] = i;
    }
}

// ---------------------------------------------------------------------------
// Step 4: grid ball query. One warp per query.
//  - per (dy,dz) row: skip if min planar dist^2 >= R2PAD; else trim x-cell
//    range to qx +- sqrt(R2PAD - dyz2) (usually 2 cells instead of 3).
//    R2PAD over-covers the reference d2's fp noise -> no false pruning.
//  - candidate test: d2 rounding identical to the verified version (on R2).
//  - selection: rank-based (count-smaller via broadcast LDS) -> same result
//    as ascending sort + take first 32, without per-step __syncwarp.
// ---------------------------------------------------------------------------
__global__ __launch_bounds__(256) void bq_kernel(const float* __restrict__ nxyz) {
    __shared__ int cand_s[8][MAXC];
    __shared__ int sorted_s[8][NS];

    int tid  = threadIdx.x;
    int warp = tid >> 5;
    int lane = tid & 31;
    int qid  = blockIdx.x * 8 + warp;
    int* cand = cand_s[warp];
    unsigned lmask = (1u << lane) - 1u;

    float qx = nxyz[3 * qid + 0];
    float qy = nxyz[3 * qid + 1];
    float qz = nxyz[3 * qid + 2];
    float q2 = __fadd_rn(__fadd_rn(__fmul_rn(qx, qx), __fmul_rn(qy, qy)),
                         __fmul_rn(qz, qz));

    int qcy = min(GD - 1, max(0, (int)(qy * (float)GD)));
    int qcz = min(GD - 1, max(0, (int)(qz * (float)GD)));

    int cnt = 0;   // warp-uniform

#pragma unroll
    for (int dz = -1; dz <= 1; dz++) {
        int cz = qcz + dz;
        if (cz < 0 || cz >= GD) continue;
        float zlo = cz * CW;
        float dzd = fmaxf(0.f, fmaxf(zlo - qz, qz - (zlo + CW)));
        float dz2 = dzd * dzd;
#pragma unroll
        for (int dy = -1; dy <= 1; dy++) {
            int cy = qcy + dy;
            if (cy < 0 || cy >= GD) continue;
            float ylo = cy * CW;
            float dyd = fmaxf(0.f, fmaxf(ylo - qy, qy - (ylo + CW)));
            float dyz2 = dz2 + dyd * dyd;
            if (dyz2 >= R2PAD) continue;          // row cannot contain a hit
            float rx = sqrtf(R2PAD - dyz2);
            int cxlo = max(0,      (int)((qx - rx) * (float)GD - 1e-3f));
            int cxhi = min(GD - 1, (int)((qx + rx) * (float)GD + 1e-3f));

            int base = (cz * GD + cy) * GD;
            int s0 = g_startc[base + cxlo];
            int s1 = g_startc[base + cxhi + 1];
            for (int j0 = s0; j0 < s1; j0 += 32) {
                int j = j0 + lane;
                bool pred = false;
                int  pidv = 0;
                if (j < s1) {
                    float4 pt = g_pts[j];
                    float dot = __fmul_rn(pt.x, qx);
                    dot = __fmaf_rn(pt.y, qy, dot);
                    dot = __fmaf_rn(pt.z, qz, dot);
                    float d2 = __fsub_rn(__fadd_rn(q2, pt.w),
                                         __fmul_rn(2.0f, dot));
                    if (d2 < R2) { pred = true; pidv = g_pid[j]; }
                }
                unsigned m = __ballot_sync(0xffffffffu, pred);
                if (m) {
                    if (pred) {
                        int pos = cnt + __popc(m & lmask);
                        if (pos < MAXC) cand[pos] = pidv;
                    }
                    cnt += __popc(m);
                }
            }
        }
    }
    if (cnt > MAXC) cnt = MAXC;
    __syncwarp();

    int outIdx, outIdn;
    if (cnt == 0) {
        outIdx = 0; outIdn = 1;
    } else {
        int* sorted = sorted_s[warp];
        for (int qi = lane; qi < cnt; qi += 32) {
            int v = cand[qi];
            int rank = 0;
            for (int j = 0; j < cnt; j++)        // broadcast LDS, conflict-free
                rank += (cand[j] < v) ? 1 : 0;   // distinct values -> distinct ranks
            if (rank < NS) sorted[rank] = v;
        }
        __syncwarp();
        int cc = cnt < NS ? cnt : NS;
        int first = sorted[0];
        outIdx = (lane < cc) ? sorted[lane] : first;
        outIdn = (lane < cc) ? 1 : 0;
    }
    g_idx[qid * NS + lane] = outIdx;
    g_idn[qid * NS + lane] = outIdn;
}

// ---------------------------------------------------------------------------
// Grouping: one block (128 threads) per query. float4 loads from g_ft into a
// stride-65 smem tile, then float4 stores per channel row (bank-conflict-free
// lane maps, verified round 7).
// ---------------------------------------------------------------------------
__global__ __launch_bounds__(128) void gather_kernel(const float* __restrict__ xyz,
                                                     const float* __restrict__ nxyz,
                                                     float* __restrict__ out) {
    __shared__ float sf[NS * 65];
    __shared__ int   si[NS];
    __shared__ int   sd[NS];

    int q    = blockIdx.x;
    int b    = q >> 11;
    int p    = q & 2047;
    int tid  = threadIdx.x;
    int warp = tid >> 5;
    int lane = tid & 31;

    if (tid < NS) {
        si[tid] = g_idx[q * NS + tid];
        sd[tid] = g_idn[q * NS + tid];
    }
    __syncthreads();

    // Load phase: each warp loads 2 feature rows per iter (16 float4 per row).
    {
        int q4   = lane & 15;
        int ssub = lane >> 4;
#pragma unroll
        for (int it = 0; it < 4; it++) {
            int s = it * 8 + warp * 2 + ssub;
            int i = si[s];
            float4 v = *(const float4*)(g_ft + (size_t)i * N_C + q4 * 4);
            float* dst = sf + s * 65 + q4 * 4;
            dst[0] = v.x; dst[1] = v.y; dst[2] = v.z; dst[3] = v.w;
        }
    }
    __syncthreads();

    if (warp == 0) {
        int i = si[lane];
        float qx = nxyz[3 * q + 0];
        float qy = nxyz[3 * q + 1];
        float qz = nxyz[3 * q + 2];
        float ox = __fsub_rn(xyz[3 * i + 0], qx);
        float oy = __fsub_rn(xyz[3 * i + 1], qy);
        float oz = __fsub_rn(xyz[3 * i + 2], qz);
        size_t base = (((size_t)b * 67 + 0) * N_P + p) * NS + lane;
        size_t chs  = (size_t)N_P * NS;
        out[base]           = ox;
        out[base + chs]     = oy;
        out[base + 2 * chs] = oz;
        out[F1_OFF + (size_t)q * NS + lane] = (float)sd[lane];
    }

    // Store phase: 64 feature channels as float4 rows (8 stores per channel).
    {
        int sg   = lane & 7;
        int csub = lane >> 3;
#pragma unroll
        for (int it = 0; it < 4; it++) {
            int ch = it * 16 + warp * 4 + csub;
            float4 v;
            v.x = sf[(4 * sg + 0) * 65 + ch];
            v.y = sf[(4 * sg + 1) * 65 + ch];
            v.z = sf[(4 * sg + 2) * 65 + ch];
            v.w = sf[(4 * sg + 3) * 65 + ch];
            *(float4*)(out + (((size_t)b * 67 + 3 + ch) * N_P + p) * NS + 4 * sg) = v;
        }
    }
}

// ---------------------------------------------------------------------------
extern "C" void kernel_launch(void* const* d_in, const int* in_sizes, int n_in,
                              void* d_out, int out_size) {
    const float* xyz  = (const float*)d_in[0];   // (20000, 3)
    const float* nxyz = (const float*)d_in[1];   // (2, 2048, 3)
    const float* feat = (const float*)d_in[2];   // (64, 20000)
    float* out = (float*)d_out;

    count_tr_kernel<<<CNT_BLOCKS + TR_BLOCKS, 256>>>(xyz, feat);
    scan_kernel<<<1, 1024>>>();
    scatter_kernel<<<(N_PTS + 255) / 256, 256>>>(xyz);
    bq_kernel<<<N_Q / 8, 256>>>(nxyz);
    gather_kernel<<<N_Q, 128>>>(xyz, nxyz, out);
}